// round 7
// baseline (speedup 1.0000x reference)
#include <cuda_runtime.h>
#include <cstddef>

// Problem dims (fixed by the dataset)
#define INSIZE  2048
#define HSIZE   4096
#define OUTSIZE 2048

// ---------------- device scratch (no allocations allowed) ----------------
__device__ float g_h1[HSIZE];
__device__ float g_m1[HSIZE];
__device__ float g_h2[HSIZE];
__device__ float g_m2[HSIZE];
__device__ float g_Et[(size_t)HSIZE * OUTSIZE];            // compacted Et rows
__device__ float g_A1[(size_t)HSIZE * HSIZE];              // W2^T[idx1][idx2]
__device__ float g_A2[(size_t)INSIZE * HSIZE];             // W1^T[:, idx1]
__device__ float g_B1[(size_t)HSIZE * OUTSIZE];            // W3^T rows idx2
__device__ int   g_idx1[HSIZE];
__device__ int   g_idx2[HSIZE];
__device__ int   g_cnt1[2];   // [raw, padded-to-32]
__device__ int   g_cnt2[2];
__device__ int   g_c2048[2] = {INSIZE, INSIZE};

// ---------------- fp32 GEMV: z = W @ v, optional ReLU mask ----------------
__global__ void gemv_kernel(const float* __restrict__ W, const float* __restrict__ v,
                            float* __restrict__ h, float* __restrict__ mask, int K)
{
    int row = blockIdx.x;
    const float* w = W + (size_t)row * K;
    float acc = 0.f;
    for (int i = threadIdx.x * 4; i < K; i += blockDim.x * 4) {
        float4 a = *(const float4*)(w + i);
        float4 b = *(const float4*)(v + i);
        acc += a.x * b.x + a.y * b.y + a.z * b.z + a.w * b.w;
    }
    __shared__ float red[256];
    red[threadIdx.x] = acc;
    __syncthreads();
    for (int s = 128; s > 0; s >>= 1) {
        if (threadIdx.x < s) red[threadIdx.x] += red[threadIdx.x + s];
        __syncthreads();
    }
    if (threadIdx.x == 0) {
        float z = red[0];
        if (mask) {
            float m = z > 0.f ? 1.f : 0.f;
            mask[row] = m;
            h[row]    = z * m;
        } else {
            h[row] = z;
        }
    }
}

// ---------------- transpose: in[R,C] -> out[C,R] ----------------
__global__ void transpose_kernel(const float* __restrict__ in, float* __restrict__ out,
                                 int R, int C)
{
    __shared__ float tile[32][33];
    int x = blockIdx.x * 32 + threadIdx.x;
    int y = blockIdx.y * 32 + threadIdx.y;
    #pragma unroll
    for (int j = 0; j < 32; j += 8)
        tile[threadIdx.y + j][threadIdx.x] = in[(size_t)(y + j) * C + x];
    __syncthreads();
    int ox = blockIdx.y * 32 + threadIdx.x;
    int oy = blockIdx.x * 32 + threadIdx.y;
    #pragma unroll
    for (int j = 0; j < 32; j += 8)
        out[(size_t)(oy + j) * R + ox] = tile[threadIdx.x][threadIdx.y + j];
}

// ---------------- diagonal write (regions pre-zeroed by memset) ----------------
__global__ void diagwrite_kernel(float* __restrict__ out,
                                 const float* __restrict__ m1, const float* __restrict__ m2,
                                 size_t offJ2, size_t offJ4, size_t offJ6)
{
    int i = blockIdx.x * 256 + threadIdx.x;
    if (i < HSIZE) {
        out[offJ2 + (size_t)i * (HSIZE + 1)] = m1[i];
        out[offJ4 + (size_t)i * (HSIZE + 1)] = m2[i];
    }
    if (i < OUTSIZE)
        out[offJ6 + (size_t)i * (OUTSIZE + 1)] = 1.0f;
}

// ---------------- build sorted index list of nonzero mask entries ----------------
__global__ void build_idx_kernel(const float* __restrict__ mask, int n,
                                 int* __restrict__ idx, int* __restrict__ cnt)
{
    __shared__ int sdata[1024];
    __shared__ int sbase;
    int tid = threadIdx.x;
    if (tid == 0) sbase = 0;
    __syncthreads();
    for (int chunk = 0; chunk < n; chunk += 1024) {
        int i = chunk + tid;
        int flag = (i < n && mask[i] != 0.f) ? 1 : 0;
        sdata[tid] = flag;
        __syncthreads();
        #pragma unroll
        for (int off = 1; off < 1024; off <<= 1) {
            int v = (tid >= off) ? sdata[tid - off] : 0;
            __syncthreads();
            sdata[tid] += v;
            __syncthreads();
        }
        int incl  = sdata[tid];
        int total = sdata[1023];
        if (flag) idx[sbase + incl - 1] = i;
        __syncthreads();
        if (tid == 0) sbase += total;
        __syncthreads();
    }
    if (tid == 0) {
        cnt[0] = sbase;
        cnt[1] = (sbase + 31) & ~31;
    }
}

// ---------------- gather kernels (pad regions filled with exact zeros) ----------------
__global__ void gatherRC_kernel(const float* __restrict__ src, int sld,
                                const int* __restrict__ ridx, const int* __restrict__ cidx,
                                const int* __restrict__ cntr, const int* __restrict__ cntc,
                                float* __restrict__ out)
{
    int r = blockIdx.x;
    int rc = cntr[0], rp = cntr[1];
    int cc = cntc[0], cp = cntc[1];
    if (r >= rp) return;
    bool ok = (r < rc);
    const float* s = src + (size_t)(ok ? ridx[r] : 0) * sld;
    float* o = out + (size_t)r * cp;
    for (int j = threadIdx.x; j < cp; j += blockDim.x)
        o[j] = (ok && j < cc) ? s[cidx[j]] : 0.f;
}

__global__ void gatherC_kernel(const float* __restrict__ src, int sld,
                               const int* __restrict__ cidx, const int* __restrict__ cntc,
                               float* __restrict__ out)
{
    int r = blockIdx.x;
    int cc = cntc[0], cp = cntc[1];
    const float* s = src + (size_t)r * sld;
    float* o = out + (size_t)r * cp;
    for (int j = threadIdx.x; j < cp; j += blockDim.x)
        o[j] = (j < cc) ? s[cidx[j]] : 0.f;
}

__global__ void gatherR_kernel(const float* __restrict__ src, int sld,
                               const int* __restrict__ ridx, const int* __restrict__ cntr,
                               float* __restrict__ out, int ncols)
{
    int r = blockIdx.x;
    int rc = cntr[0], rp = cntr[1];
    if (r >= rp) return;
    bool ok = (r < rc);
    const float* s = src + (size_t)(ok ? ridx[r] : 0) * sld;
    float* o = out + (size_t)r * ncols;
    for (int j = threadIdx.x * 4; j < ncols; j += blockDim.x * 4) {
        float4 v = ok ? *(const float4*)(s + j) : make_float4(0.f, 0.f, 0.f, 0.f);
        *(float4*)(o + j) = v;
    }
}

// ---------------- tf32 tensor-core GEMM, 4 warps x 64x64 warp tiles ----------------
// C[M,N] = A[M,K] @ B[K,N]; K = kp[1] (mult of 32), blocks with row-base >= mp[1] exit.
// N fixed = 2048. Block tile 128x128x32, 128 threads, warp 64x64 via m16n8k8.
// 1.0 LDS per HMMA (vs 1.5 in the 8-warp 32x64 version) -> issue-bound speedup.
#define BM  128
#define BN  128
#define BKT 32
#define NDIM 2048
#define ASTR 36
#define BSTR 136

__device__ __forceinline__ unsigned f2tf32(float f) {
    unsigned r;
    asm volatile("cvt.rna.tf32.f32 %0, %1;" : "=r"(r) : "f"(f));
    return r;
}

__global__ __launch_bounds__(128)
void tf32gemm_kernel(const int* __restrict__ kp, const int* __restrict__ mp,
                     const float* __restrict__ A, const float* __restrict__ B,
                     float* __restrict__ C)
{
    if ((int)(blockIdx.y * BM) >= mp[1]) return;
    const int K = kp[1];

    __shared__ unsigned As[BM * ASTR];
    __shared__ unsigned Bs[BKT * BSTR];

    const int tid  = threadIdx.x;
    const int wid  = tid / 32;
    const int lane = tid % 32;
    const int g    = lane >> 2;    // 0..7
    const int t    = lane & 3;     // 0..3
    const int warpM = wid & 1;     // 2 warps along M -> 64 rows each
    const int warpN = wid >> 1;    // 2 warps along N -> 64 cols each

    const size_t aBase = (size_t)blockIdx.y * BM * K;
    const size_t cBase = (size_t)blockIdx.y * BM * NDIM + blockIdx.x * BN;
    const int    bCol  = blockIdx.x * BN;

    // global-load coords (128 threads)
    const int arow0 = tid >> 3;          // 0..15 (16 rows/pass, 8 passes)
    const int acol  = (tid & 7) * 4;     // 0..28
    // B: id = tid + p*128; row = id>>5 (0..31), col=(id&31)*4

    float acc[4][8][4];
    #pragma unroll
    for (int i = 0; i < 4; i++)
        #pragma unroll
        for (int j = 0; j < 8; j++)
            #pragma unroll
            for (int q = 0; q < 4; q++) acc[i][j][q] = 0.f;

    for (int bk = 0; bk < K; bk += BKT) {
        // A tile: 128x32
        #pragma unroll
        for (int p = 0; p < 8; p++) {
            int row = arow0 + p * 16;
            float4 v = *(const float4*)(&A[aBase + (size_t)row * K + bk + acol]);
            uint4 u = make_uint4(f2tf32(v.x), f2tf32(v.y), f2tf32(v.z), f2tf32(v.w));
            *(uint4*)(&As[row * ASTR + acol]) = u;
        }
        // B tile: 32x128
        #pragma unroll
        for (int p = 0; p < 8; p++) {
            int id = tid + p * 128;
            int row = id >> 5;
            int col = (id & 31) * 4;
            float4 v = *(const float4*)(&B[(size_t)(bk + row) * NDIM + bCol + col]);
            uint4 u = make_uint4(f2tf32(v.x), f2tf32(v.y), f2tf32(v.z), f2tf32(v.w));
            *(uint4*)(&Bs[row * BSTR + col]) = u;
        }
        __syncthreads();

        #pragma unroll
        for (int kk = 0; kk < BKT; kk += 8) {
            unsigned a[4][4];
            #pragma unroll
            for (int i = 0; i < 4; i++) {
                int mb = warpM * 64 + i * 16;
                a[i][0] = As[(mb + g)     * ASTR + kk + t];
                a[i][1] = As[(mb + g + 8) * ASTR + kk + t];
                a[i][2] = As[(mb + g)     * ASTR + kk + t + 4];
                a[i][3] = As[(mb + g + 8) * ASTR + kk + t + 4];
            }
            unsigned b[8][2];
            #pragma unroll
            for (int j = 0; j < 8; j++) {
                int nb = warpN * 64 + j * 8;
                b[j][0] = Bs[(kk + t)     * BSTR + nb + g];
                b[j][1] = Bs[(kk + t + 4) * BSTR + nb + g];
            }
            #pragma unroll
            for (int i = 0; i < 4; i++)
                #pragma unroll
                for (int j = 0; j < 8; j++) {
                    asm volatile(
                        "mma.sync.aligned.m16n8k8.row.col.f32.tf32.tf32.f32 "
                        "{%0,%1,%2,%3}, {%4,%5,%6,%7}, {%8,%9}, {%0,%1,%2,%3};"
                        : "+f"(acc[i][j][0]), "+f"(acc[i][j][1]),
                          "+f"(acc[i][j][2]), "+f"(acc[i][j][3])
                        : "r"(a[i][0]), "r"(a[i][1]), "r"(a[i][2]), "r"(a[i][3]),
                          "r"(b[j][0]), "r"(b[j][1]));
                }
        }
        __syncthreads();
    }

    #pragma unroll
    for (int i = 0; i < 4; i++) {
        int row0 = warpM * 64 + i * 16 + g;
        #pragma unroll
        for (int j = 0; j < 8; j++) {
            int col = warpN * 64 + j * 8 + t * 2;
            *(float2*)(&C[cBase + (size_t)row0 * NDIM + col]) =
                make_float2(acc[i][j][0], acc[i][j][1]);
            *(float2*)(&C[cBase + (size_t)(row0 + 8) * NDIM + col]) =
                make_float2(acc[i][j][2], acc[i][j][3]);
        }
    }
}

// ---------------- launch ----------------
extern "C" void kernel_launch(void* const* d_in, const int* in_sizes, int n_in,
                              void* d_out, int out_size)
{
    (void)in_sizes; (void)n_in; (void)out_size;
    const float* x  = (const float*)d_in[0];
    const float* W1 = (const float*)d_in[1];   // [4096, 2048]
    const float* W2 = (const float*)d_in[2];   // [4096, 4096]
    const float* W3 = (const float*)d_in[3];   // [2048, 4096]
    float* out = (float*)d_out;

    float *h1, *m1, *h2, *m2, *Et, *A1, *A2, *B1;
    int *idx1, *idx2, *cnt1, *cnt2, *c2048;
    cudaGetSymbolAddress((void**)&h1, g_h1);
    cudaGetSymbolAddress((void**)&m1, g_m1);
    cudaGetSymbolAddress((void**)&h2, g_h2);
    cudaGetSymbolAddress((void**)&m2, g_m2);
    cudaGetSymbolAddress((void**)&Et, g_Et);
    cudaGetSymbolAddress((void**)&A1, g_A1);
    cudaGetSymbolAddress((void**)&A2, g_A2);
    cudaGetSymbolAddress((void**)&B1, g_B1);
    cudaGetSymbolAddress((void**)&idx1, g_idx1);
    cudaGetSymbolAddress((void**)&idx2, g_idx2);
    cudaGetSymbolAddress((void**)&cnt1, g_cnt1);
    cudaGetSymbolAddress((void**)&cnt2, g_cnt2);
    cudaGetSymbolAddress((void**)&c2048, g_c2048);

    // Output offsets (floats)
    const size_t OFF_OUT = 0;                                        // [1, 2048]
    const size_t OFF_DJM = OFF_OUT + OUTSIZE;                        // [2048, 2048]
    const size_t OFF_J1  = OFF_DJM + (size_t)INSIZE * OUTSIZE;       // W1^T [2048, 4096]
    const size_t OFF_J2  = OFF_J1  + (size_t)INSIZE * HSIZE;         // diag(m1) [4096, 4096]
    const size_t OFF_J3  = OFF_J2  + (size_t)HSIZE * HSIZE;          // W2^T [4096, 4096]
    const size_t OFF_J4  = OFF_J3  + (size_t)HSIZE * HSIZE;          // diag(m2) [4096, 4096]
    const size_t OFF_J5  = OFF_J4  + (size_t)HSIZE * HSIZE;          // W3^T [4096, 2048]
    const size_t OFF_J6  = OFF_J5  + (size_t)HSIZE * OUTSIZE;        // eye [2048, 2048]

    // Forward pass (fp32 GEMVs; exact masks matter for correctness)
    gemv_kernel<<<HSIZE,   256>>>(W1, x,  h1, m1, INSIZE);
    gemv_kernel<<<HSIZE,   256>>>(W2, h1, h2, m2, HSIZE);
    gemv_kernel<<<OUTSIZE, 256>>>(W3, h2, out + OFF_OUT, nullptr, HSIZE);

    // Jacobian transposes into output slots (reused as gather sources)
    {
        dim3 blk(32, 8);
        transpose_kernel<<<dim3(INSIZE/32, HSIZE/32), blk>>>(W1, out + OFF_J1, HSIZE, INSIZE);
        transpose_kernel<<<dim3(HSIZE/32,  HSIZE/32), blk>>>(W2, out + OFF_J3, HSIZE, HSIZE);
        transpose_kernel<<<dim3(HSIZE/32,  OUTSIZE/32), blk>>>(W3, out + OFF_J5, OUTSIZE, HSIZE);
    }
    // Diagonal blocks: memset (fast graph memset nodes) + tiny diagonal write
    cudaMemsetAsync(out + OFF_J2, 0, (size_t)HSIZE * HSIZE * sizeof(float));
    cudaMemsetAsync(out + OFF_J4, 0, (size_t)HSIZE * HSIZE * sizeof(float));
    cudaMemsetAsync(out + OFF_J6, 0, (size_t)OUTSIZE * OUTSIZE * sizeof(float));
    diagwrite_kernel<<<(HSIZE + 255) / 256, 256>>>(out, m1, m2, OFF_J2, OFF_J4, OFF_J6);

    // Sparsity compaction: ReLU masks kill ~half the rows/cols of the chain.
    build_idx_kernel<<<1, 1024>>>(m1, HSIZE, idx1, cnt1);
    build_idx_kernel<<<1, 1024>>>(m2, HSIZE, idx2, cnt2);
    // A1[n1p, n2p] = W2^T[idx1, idx2]
    gatherRC_kernel<<<HSIZE, 256>>>(out + OFF_J3, HSIZE, idx1, idx2, cnt1, cnt2, A1);
    // B1[n2p, 2048] = W3^T[idx2, :]
    gatherR_kernel<<<HSIZE, 256>>>(out + OFF_J5, OUTSIZE, idx2, cnt2, B1, OUTSIZE);
    // A2[2048, n1p] = W1^T[:, idx1]
    gatherC_kernel<<<INSIZE, 256>>>(out + OFF_J1, HSIZE, idx1, cnt1, A2);

    // GEMM1: Et[n1p, 2048] = A1 @ B1   (K = n2p, M-limit = n1p)
    tf32gemm_kernel<<<dim3(NDIM / BN, HSIZE / BM), 128>>>(cnt2, cnt1, A1, B1, Et);
    // GEMM2: DJM[2048, 2048] = A2 @ Et (K = n1p)
    tf32gemm_kernel<<<dim3(NDIM / BN, INSIZE / BM), 128>>>(cnt1, c2048, A2, Et, out + OFF_DJM);
}

// round 8
// speedup vs baseline: 1.3219x; 1.3219x over previous
#include <cuda_runtime.h>
#include <cstddef>

// Problem dims (fixed by the dataset)
#define INSIZE  2048
#define HSIZE   4096
#define OUTSIZE 2048

// ---------------- device scratch (no allocations allowed) ----------------
__device__ float g_h1[HSIZE];
__device__ float g_m1[HSIZE];
__device__ float g_h2[HSIZE];
__device__ float g_m2[HSIZE];
__device__ float g_Et[(size_t)HSIZE * OUTSIZE];
__device__ float g_A1[(size_t)HSIZE * HSIZE];
__device__ float g_A2[(size_t)INSIZE * HSIZE];
__device__ float g_B1[(size_t)HSIZE * OUTSIZE];
__device__ int   g_idx1[HSIZE];
__device__ int   g_idx2[HSIZE];
__device__ int   g_cnt1[2];
__device__ int   g_cnt2[2];
__device__ int   g_c2048[2] = {INSIZE, INSIZE};

// ---------------- fp32 GEMV: z = W @ v, optional ReLU mask ----------------
__global__ void gemv_kernel(const float* __restrict__ W, const float* __restrict__ v,
                            float* __restrict__ h, float* __restrict__ mask, int K)
{
    int row = blockIdx.x;
    const float* w = W + (size_t)row * K;
    float acc = 0.f;
    for (int i = threadIdx.x * 4; i < K; i += blockDim.x * 4) {
        float4 a = *(const float4*)(w + i);
        float4 b = *(const float4*)(v + i);
        acc += a.x * b.x + a.y * b.y + a.z * b.z + a.w * b.w;
    }
    __shared__ float red[256];
    red[threadIdx.x] = acc;
    __syncthreads();
    for (int s = 128; s > 0; s >>= 1) {
        if (threadIdx.x < s) red[threadIdx.x] += red[threadIdx.x + s];
        __syncthreads();
    }
    if (threadIdx.x == 0) {
        float z = red[0];
        if (mask) {
            float m = z > 0.f ? 1.f : 0.f;
            mask[row] = m;
            h[row]    = z * m;
        } else {
            h[row] = z;
        }
    }
}

// ---------------- transpose: in[R,C] -> out[C,R] ----------------
__global__ void transpose_kernel(const float* __restrict__ in, float* __restrict__ out,
                                 int R, int C)
{
    __shared__ float tile[32][33];
    int x = blockIdx.x * 32 + threadIdx.x;
    int y = blockIdx.y * 32 + threadIdx.y;
    #pragma unroll
    for (int j = 0; j < 32; j += 8)
        tile[threadIdx.y + j][threadIdx.x] = in[(size_t)(y + j) * C + x];
    __syncthreads();
    int ox = blockIdx.y * 32 + threadIdx.x;
    int oy = blockIdx.x * 32 + threadIdx.y;
    #pragma unroll
    for (int j = 0; j < 32; j += 8)
        out[(size_t)(oy + j) * R + ox] = tile[threadIdx.x][threadIdx.y + j];
}

// ---------------- diag fill: out[N,N] = diag(d) (d==nullptr -> identity) ----------------
__global__ void diagfill_kernel(float* __restrict__ out, const float* __restrict__ d, int N)
{
    size_t idx = ((size_t)blockIdx.x * blockDim.x + threadIdx.x) * 4;
    size_t total = (size_t)N * N;
    if (idx >= total) return;
    size_t row = idx / N;
    size_t col = idx - row * N;
    float4 v = make_float4(0.f, 0.f, 0.f, 0.f);
    if (row >= col && row < col + 4) {
        float dv = d ? d[row] : 1.0f;
        ((float*)&v)[row - col] = dv;
    }
    *(float4*)(out + idx) = v;
}

// ---------------- build sorted index list of nonzero mask entries ----------------
__global__ void build_idx_kernel(const float* __restrict__ mask, int n,
                                 int* __restrict__ idx, int* __restrict__ cnt)
{
    __shared__ int sdata[1024];
    __shared__ int sbase;
    int tid = threadIdx.x;
    if (tid == 0) sbase = 0;
    __syncthreads();
    for (int chunk = 0; chunk < n; chunk += 1024) {
        int i = chunk + tid;
        int flag = (i < n && mask[i] != 0.f) ? 1 : 0;
        sdata[tid] = flag;
        __syncthreads();
        #pragma unroll
        for (int off = 1; off < 1024; off <<= 1) {
            int v = (tid >= off) ? sdata[tid - off] : 0;
            __syncthreads();
            sdata[tid] += v;
            __syncthreads();
        }
        int incl  = sdata[tid];
        int total = sdata[1023];
        if (flag) idx[sbase + incl - 1] = i;
        __syncthreads();
        if (tid == 0) sbase += total;
        __syncthreads();
    }
    if (tid == 0) {
        cnt[0] = sbase;
        cnt[1] = (sbase + 31) & ~31;
    }
}

// ---------------- gather kernels (pad regions filled with exact zeros) ----------------
__global__ void gatherRC_kernel(const float* __restrict__ src, int sld,
                                const int* __restrict__ ridx, const int* __restrict__ cidx,
                                const int* __restrict__ cntr, const int* __restrict__ cntc,
                                float* __restrict__ out)
{
    int r = blockIdx.x;
    int rc = cntr[0], rp = cntr[1];
    int cc = cntc[0], cp = cntc[1];
    if (r >= rp) return;
    bool ok = (r < rc);
    const float* s = src + (size_t)(ok ? ridx[r] : 0) * sld;
    float* o = out + (size_t)r * cp;
    for (int j = threadIdx.x; j < cp; j += blockDim.x)
        o[j] = (ok && j < cc) ? s[cidx[j]] : 0.f;
}

__global__ void gatherC_kernel(const float* __restrict__ src, int sld,
                               const int* __restrict__ cidx, const int* __restrict__ cntc,
                               float* __restrict__ out)
{
    int r = blockIdx.x;
    int cc = cntc[0], cp = cntc[1];
    const float* s = src + (size_t)r * sld;
    float* o = out + (size_t)r * cp;
    for (int j = threadIdx.x; j < cp; j += blockDim.x)
        o[j] = (j < cc) ? s[cidx[j]] : 0.f;
}

__global__ void gatherR_kernel(const float* __restrict__ src, int sld,
                               const int* __restrict__ ridx, const int* __restrict__ cntr,
                               float* __restrict__ out, int ncols)
{
    int r = blockIdx.x;
    int rc = cntr[0], rp = cntr[1];
    if (r >= rp) return;
    bool ok = (r < rc);
    const float* s = src + (size_t)(ok ? ridx[r] : 0) * sld;
    float* o = out + (size_t)r * ncols;
    for (int j = threadIdx.x * 4; j < ncols; j += blockDim.x * 4) {
        float4 v = ok ? *(const float4*)(s + j) : make_float4(0.f, 0.f, 0.f, 0.f);
        *(float4*)(o + j) = v;
    }
}

// ---------------- tf32 tensor-core GEMM (round-3 exact: 8 warps x 32x64) ----------------
#define BM  128
#define BN  128
#define BKT 32
#define NDIM 2048
#define ASTR 36
#define BSTR 136

__device__ __forceinline__ unsigned f2tf32(float f) {
    unsigned r;
    asm volatile("cvt.rna.tf32.f32 %0, %1;" : "=r"(r) : "f"(f));
    return r;
}

__global__ __launch_bounds__(256)
void tf32gemm_kernel(const int* __restrict__ kp, const int* __restrict__ mp,
                     const float* __restrict__ A, const float* __restrict__ B,
                     float* __restrict__ C)
{
    if ((int)(blockIdx.y * BM) >= mp[1]) return;
    const int K = kp[1];

    __shared__ unsigned As[BM * ASTR];
    __shared__ unsigned Bs[BKT * BSTR];

    const int tid  = threadIdx.x;
    const int wid  = tid / 32;
    const int lane = tid % 32;
    const int g    = lane >> 2;
    const int t    = lane & 3;

    const int warpM = wid % 4;
    const int warpN = wid / 4;

    const size_t aBase = (size_t)blockIdx.y * BM * K;
    const size_t cBase = (size_t)blockIdx.y * BM * NDIM + blockIdx.x * BN;
    const int    bCol  = blockIdx.x * BN;

    const int arow = tid / 8;
    const int acol = (tid % 8) * 4;
    const int brow = tid / 32;
    const int bcol = (tid % 32) * 4;

    float acc[2][8][4];
    #pragma unroll
    for (int i = 0; i < 2; i++)
        #pragma unroll
        for (int j = 0; j < 8; j++)
            #pragma unroll
            for (int q = 0; q < 4; q++) acc[i][j][q] = 0.f;

    for (int bk = 0; bk < K; bk += BKT) {
        #pragma unroll
        for (int r = 0; r < 4; r++) {
            int row = arow + r * 32;
            float4 v = *(const float4*)(&A[aBase + (size_t)row * K + bk + acol]);
            unsigned* dst = &As[row * ASTR + acol];
            dst[0] = f2tf32(v.x); dst[1] = f2tf32(v.y);
            dst[2] = f2tf32(v.z); dst[3] = f2tf32(v.w);
        }
        #pragma unroll
        for (int r = 0; r < 4; r++) {
            int row = brow + r * 8;
            float4 v = *(const float4*)(&B[(size_t)(bk + row) * NDIM + bCol + bcol]);
            unsigned* dst = &Bs[row * BSTR + bcol];
            dst[0] = f2tf32(v.x); dst[1] = f2tf32(v.y);
            dst[2] = f2tf32(v.z); dst[3] = f2tf32(v.w);
        }
        __syncthreads();

        #pragma unroll
        for (int kk = 0; kk < BKT; kk += 8) {
            unsigned a[2][4];
            #pragma unroll
            for (int i = 0; i < 2; i++) {
                int mb = warpM * 32 + i * 16;
                a[i][0] = As[(mb + g)     * ASTR + kk + t];
                a[i][1] = As[(mb + g + 8) * ASTR + kk + t];
                a[i][2] = As[(mb + g)     * ASTR + kk + t + 4];
                a[i][3] = As[(mb + g + 8) * ASTR + kk + t + 4];
            }
            unsigned b[8][2];
            #pragma unroll
            for (int j = 0; j < 8; j++) {
                int nb = warpN * 64 + j * 8;
                b[j][0] = Bs[(kk + t)     * BSTR + nb + g];
                b[j][1] = Bs[(kk + t + 4) * BSTR + nb + g];
            }
            #pragma unroll
            for (int i = 0; i < 2; i++)
                #pragma unroll
                for (int j = 0; j < 8; j++) {
                    asm volatile(
                        "mma.sync.aligned.m16n8k8.row.col.f32.tf32.tf32.f32 "
                        "{%0,%1,%2,%3}, {%4,%5,%6,%7}, {%8,%9}, {%0,%1,%2,%3};"
                        : "+f"(acc[i][j][0]), "+f"(acc[i][j][1]),
                          "+f"(acc[i][j][2]), "+f"(acc[i][j][3])
                        : "r"(a[i][0]), "r"(a[i][1]), "r"(a[i][2]), "r"(a[i][3]),
                          "r"(b[j][0]), "r"(b[j][1]));
                }
        }
        __syncthreads();
    }

    #pragma unroll
    for (int i = 0; i < 2; i++) {
        int row0 = warpM * 32 + i * 16 + g;
        #pragma unroll
        for (int j = 0; j < 8; j++) {
            int col = warpN * 64 + j * 8 + t * 2;
            *(float2*)(&C[cBase + (size_t)row0 * NDIM + col]) =
                make_float2(acc[i][j][0], acc[i][j][1]);
            *(float2*)(&C[cBase + (size_t)(row0 + 8) * NDIM + col]) =
                make_float2(acc[i][j][2], acc[i][j][3]);
        }
    }
}

// ---------------- launch ----------------
extern "C" void kernel_launch(void* const* d_in, const int* in_sizes, int n_in,
                              void* d_out, int out_size)
{
    (void)in_sizes; (void)n_in; (void)out_size;
    const float* x  = (const float*)d_in[0];
    const float* W1 = (const float*)d_in[1];   // [4096, 2048]
    const float* W2 = (const float*)d_in[2];   // [4096, 4096]
    const float* W3 = (const float*)d_in[3];   // [2048, 4096]
    float* out = (float*)d_out;

    float *h1, *m1, *h2, *m2, *Et, *A1, *A2, *B1;
    int *idx1, *idx2, *cnt1, *cnt2, *c2048;
    cudaGetSymbolAddress((void**)&h1, g_h1);
    cudaGetSymbolAddress((void**)&m1, g_m1);
    cudaGetSymbolAddress((void**)&h2, g_h2);
    cudaGetSymbolAddress((void**)&m2, g_m2);
    cudaGetSymbolAddress((void**)&Et, g_Et);
    cudaGetSymbolAddress((void**)&A1, g_A1);
    cudaGetSymbolAddress((void**)&A2, g_A2);
    cudaGetSymbolAddress((void**)&B1, g_B1);
    cudaGetSymbolAddress((void**)&idx1, g_idx1);
    cudaGetSymbolAddress((void**)&idx2, g_idx2);
    cudaGetSymbolAddress((void**)&cnt1, g_cnt1);
    cudaGetSymbolAddress((void**)&cnt2, g_cnt2);
    cudaGetSymbolAddress((void**)&c2048, g_c2048);

    // Output offsets (floats)
    const size_t OFF_OUT = 0;                                        // [1, 2048]
    const size_t OFF_DJM = OFF_OUT + OUTSIZE;                        // [2048, 2048]
    const size_t OFF_J1  = OFF_DJM + (size_t)INSIZE * OUTSIZE;       // W1^T [2048, 4096]
    const size_t OFF_J2  = OFF_J1  + (size_t)INSIZE * HSIZE;         // diag(m1)
    const size_t OFF_J3  = OFF_J2  + (size_t)HSIZE * HSIZE;          // W2^T
    const size_t OFF_J4  = OFF_J3  + (size_t)HSIZE * HSIZE;          // diag(m2)
    const size_t OFF_J5  = OFF_J4  + (size_t)HSIZE * HSIZE;          // W3^T
    const size_t OFF_J6  = OFF_J5  + (size_t)HSIZE * OUTSIZE;        // eye

    // ---- capture-safe fork: two side streams joined before return ----
    cudaStream_t sT, sD;
    cudaStreamCreateWithFlags(&sT, cudaStreamNonBlocking);
    cudaStreamCreateWithFlags(&sD, cudaStreamNonBlocking);
    cudaEvent_t e0, eT, eM, eD;
    cudaEventCreateWithFlags(&e0, cudaEventDisableTiming);
    cudaEventCreateWithFlags(&eT, cudaEventDisableTiming);
    cudaEventCreateWithFlags(&eM, cudaEventDisableTiming);
    cudaEventCreateWithFlags(&eD, cudaEventDisableTiming);

    // fork point (captures current head of the main stream)
    cudaEventRecord(e0, 0);
    cudaStreamWaitEvent(sT, e0, 0);
    cudaStreamWaitEvent(sD, e0, 0);

    // Branch T: Jacobian transposes (depend only on inputs), concurrent with GEMVs
    {
        dim3 blk(32, 8);
        transpose_kernel<<<dim3(INSIZE/32, HSIZE/32), blk, 0, sT>>>(W1, out + OFF_J1, HSIZE, INSIZE);
        transpose_kernel<<<dim3(HSIZE/32,  HSIZE/32), blk, 0, sT>>>(W2, out + OFF_J3, HSIZE, HSIZE);
        transpose_kernel<<<dim3(HSIZE/32,  OUTSIZE/32), blk, 0, sT>>>(W3, out + OFF_J5, OUTSIZE, HSIZE);
        cudaEventRecord(eT, sT);
    }

    // Main: forward GEMV chain (fp32; exact masks)
    gemv_kernel<<<HSIZE,   256>>>(W1, x,  h1, m1, INSIZE);
    gemv_kernel<<<HSIZE,   256>>>(W2, h1, h2, m2, HSIZE);
    cudaEventRecord(eM, 0);                       // masks m1, m2 ready
    gemv_kernel<<<OUTSIZE, 256>>>(W3, h2, out + OFF_OUT, nullptr, HSIZE);

    // Branch D: identity block immediately; mask-diagonals after eM.
    // Runs concurrent with gathers + tensor-bound GEMMs (memory vs tensor pipes).
    {
        size_t nH = ((size_t)HSIZE * HSIZE) / 4;
        size_t nO = ((size_t)OUTSIZE * OUTSIZE) / 4;
        diagfill_kernel<<<(unsigned)((nO + 255) / 256), 256, 0, sD>>>(out + OFF_J6, nullptr, OUTSIZE);
        cudaStreamWaitEvent(sD, eM, 0);
        diagfill_kernel<<<(unsigned)((nH + 255) / 256), 256, 0, sD>>>(out + OFF_J2, m1, HSIZE);
        diagfill_kernel<<<(unsigned)((nH + 255) / 256), 256, 0, sD>>>(out + OFF_J4, m2, HSIZE);
        cudaEventRecord(eD, sD);
    }

    // Main: compaction (needs masks) then gathers (need transposes too)
    build_idx_kernel<<<1, 1024>>>(m1, HSIZE, idx1, cnt1);
    build_idx_kernel<<<1, 1024>>>(m2, HSIZE, idx2, cnt2);
    cudaStreamWaitEvent(0, eT, 0);
    gatherRC_kernel<<<HSIZE, 256>>>(out + OFF_J3, HSIZE, idx1, idx2, cnt1, cnt2, A1);
    gatherR_kernel<<<HSIZE, 256>>>(out + OFF_J5, OUTSIZE, idx2, cnt2, B1, OUTSIZE);
    gatherC_kernel<<<INSIZE, 256>>>(out + OFF_J1, HSIZE, idx1, cnt1, A2);

    // GEMM1: Et[n1p, 2048] = A1 @ B1   (K = n2p, M-limit = n1p)
    tf32gemm_kernel<<<dim3(NDIM / BN, HSIZE / BM), 256>>>(cnt2, cnt1, A1, B1, Et);
    // GEMM2: DJM[2048, 2048] = A2 @ Et (K = n1p)
    tf32gemm_kernel<<<dim3(NDIM / BN, INSIZE / BM), 256>>>(cnt1, c2048, A2, Et, out + OFF_DJM);

    // join branch D
    cudaStreamWaitEvent(0, eD, 0);

    cudaEventDestroy(e0); cudaEventDestroy(eT);
    cudaEventDestroy(eM); cudaEventDestroy(eD);
    cudaStreamDestroy(sT); cudaStreamDestroy(sD);
}

// round 9
// speedup vs baseline: 1.8002x; 1.3618x over previous
#include <cuda_runtime.h>
#include <cuda_fp16.h>
#include <cstddef>

// Problem dims (fixed by the dataset)
#define INSIZE  2048
#define HSIZE   4096
#define OUTSIZE 2048

// ---------------- device scratch (no allocations allowed) ----------------
__device__ float  g_h1[HSIZE];
__device__ float  g_m1[HSIZE];
__device__ float  g_h2[HSIZE];
__device__ float  g_m2[HSIZE];
__device__ __half g_Et[(size_t)HSIZE * OUTSIZE];   // Et[n1pad][2048] fp16
__device__ __half g_A1[(size_t)HSIZE * HSIZE];     // W2^T[idx1][idx2] fp16
__device__ __half g_A2[(size_t)INSIZE * HSIZE];    // W1^T[:, idx1] fp16
__device__ __half g_B1[(size_t)HSIZE * OUTSIZE];   // W3^T rows idx2 fp16
__device__ int    g_idx1[HSIZE];
__device__ int    g_idx2[HSIZE];
__device__ int    g_cnt1[2];   // [raw, padded-to-32]
__device__ int    g_cnt2[2];
__device__ int    g_c2048[2] = {INSIZE, INSIZE};

// ---------------- fp32 GEMV: z = W @ v, optional ReLU mask ----------------
__global__ void gemv_kernel(const float* __restrict__ W, const float* __restrict__ v,
                            float* __restrict__ h, float* __restrict__ mask, int K)
{
    int row = blockIdx.x;
    const float* w = W + (size_t)row * K;
    float acc = 0.f;
    for (int i = threadIdx.x * 4; i < K; i += blockDim.x * 4) {
        float4 a = *(const float4*)(w + i);
        float4 b = *(const float4*)(v + i);
        acc += a.x * b.x + a.y * b.y + a.z * b.z + a.w * b.w;
    }
    __shared__ float red[256];
    red[threadIdx.x] = acc;
    __syncthreads();
    for (int s = 128; s > 0; s >>= 1) {
        if (threadIdx.x < s) red[threadIdx.x] += red[threadIdx.x + s];
        __syncthreads();
    }
    if (threadIdx.x == 0) {
        float z = red[0];
        if (mask) {
            float m = z > 0.f ? 1.f : 0.f;
            mask[row] = m;
            h[row]    = z * m;
        } else {
            h[row] = z;
        }
    }
}

// ---------------- transpose: in[R,C] -> out[C,R] ----------------
__global__ void transpose_kernel(const float* __restrict__ in, float* __restrict__ out,
                                 int R, int C)
{
    __shared__ float tile[32][33];
    int x = blockIdx.x * 32 + threadIdx.x;
    int y = blockIdx.y * 32 + threadIdx.y;
    #pragma unroll
    for (int j = 0; j < 32; j += 8)
        tile[threadIdx.y + j][threadIdx.x] = in[(size_t)(y + j) * C + x];
    __syncthreads();
    int ox = blockIdx.y * 32 + threadIdx.x;
    int oy = blockIdx.x * 32 + threadIdx.y;
    #pragma unroll
    for (int j = 0; j < 32; j += 8)
        out[(size_t)(oy + j) * R + ox] = tile[threadIdx.x][threadIdx.y + j];
}

// ---------------- diag fill: out[N,N] = diag(d) (d==nullptr -> identity) ----------------
__global__ void diagfill_kernel(float* __restrict__ out, const float* __restrict__ d, int N)
{
    size_t idx = ((size_t)blockIdx.x * blockDim.x + threadIdx.x) * 4;
    size_t total = (size_t)N * N;
    if (idx >= total) return;
    size_t row = idx / N;
    size_t col = idx - row * N;
    float4 v = make_float4(0.f, 0.f, 0.f, 0.f);
    if (row >= col && row < col + 4) {
        float dv = d ? d[row] : 1.0f;
        ((float*)&v)[row - col] = dv;
    }
    *(float4*)(out + idx) = v;
}

// ---------------- build sorted index list of nonzero mask entries ----------------
__global__ void build_idx_kernel(const float* __restrict__ mask, int n,
                                 int* __restrict__ idx, int* __restrict__ cnt)
{
    __shared__ int sdata[1024];
    __shared__ int sbase;
    int tid = threadIdx.x;
    if (tid == 0) sbase = 0;
    __syncthreads();
    for (int chunk = 0; chunk < n; chunk += 1024) {
        int i = chunk + tid;
        int flag = (i < n && mask[i] != 0.f) ? 1 : 0;
        sdata[tid] = flag;
        __syncthreads();
        #pragma unroll
        for (int off = 1; off < 1024; off <<= 1) {
            int v = (tid >= off) ? sdata[tid - off] : 0;
            __syncthreads();
            sdata[tid] += v;
            __syncthreads();
        }
        int incl  = sdata[tid];
        int total = sdata[1023];
        if (flag) idx[sbase + incl - 1] = i;
        __syncthreads();
        if (tid == 0) sbase += total;
        __syncthreads();
    }
    if (tid == 0) {
        cnt[0] = sbase;
        cnt[1] = (sbase + 31) & ~31;
    }
}

// ---------------- gather kernels -> fp16 outputs (pad exact zeros) ----------------
__global__ void gatherRC_kernel(const float* __restrict__ src, int sld,
                                const int* __restrict__ ridx, const int* __restrict__ cidx,
                                const int* __restrict__ cntr, const int* __restrict__ cntc,
                                __half* __restrict__ out)
{
    int r = blockIdx.x;
    int rc = cntr[0], rp = cntr[1];
    int cc = cntc[0], cp = cntc[1];
    if (r >= rp) return;
    bool ok = (r < rc);
    const float* s = src + (size_t)(ok ? ridx[r] : 0) * sld;
    __half* o = out + (size_t)r * cp;
    for (int j = threadIdx.x; j < cp; j += blockDim.x)
        o[j] = (ok && j < cc) ? __float2half_rn(s[cidx[j]]) : __float2half_rn(0.f);
}

__global__ void gatherC_kernel(const float* __restrict__ src, int sld,
                               const int* __restrict__ cidx, const int* __restrict__ cntc,
                               __half* __restrict__ out)
{
    int r = blockIdx.x;
    int cc = cntc[0], cp = cntc[1];
    const float* s = src + (size_t)r * sld;
    __half* o = out + (size_t)r * cp;
    for (int j = threadIdx.x; j < cp; j += blockDim.x)
        o[j] = (j < cc) ? __float2half_rn(s[cidx[j]]) : __float2half_rn(0.f);
}

__global__ void gatherR_kernel(const float* __restrict__ src, int sld,
                               const int* __restrict__ ridx, const int* __restrict__ cntr,
                               __half* __restrict__ out, int ncols)
{
    int r = blockIdx.x;
    int rc = cntr[0], rp = cntr[1];
    if (r >= rp) return;
    bool ok = (r < rc);
    const float* s = src + (size_t)(ok ? ridx[r] : 0) * sld;
    __half* o = out + (size_t)r * ncols;
    for (int j = threadIdx.x * 4; j < ncols; j += blockDim.x * 4) {
        float4 v = ok ? *(const float4*)(s + j) : make_float4(0.f, 0.f, 0.f, 0.f);
        __half2 lo = __floats2half2_rn(v.x, v.y);
        __half2 hi = __floats2half2_rn(v.z, v.w);
        *(__half2*)(o + j)     = lo;
        *(__half2*)(o + j + 2) = hi;
    }
}

// ---------------- fp16 tensor-core GEMM: m16n8k16, 8 warps x 32x64 ----------------
// C[M,N] = A[M,K] @ B[K,N]; A,B fp16 (K-padded to 32); K = kp[1]; blocks with
// row-base >= mp[1] exit. N fixed = 2048. Output fp32 or fp16 (template).
#define BM  128
#define BN  128
#define BKT 32      // k elements per tile
#define NDIM 2048
#define AST 20      // uint32 stride As32 (16 data + 4 pad) : g*20+t distinct mod 32
#define BST 136     // uint32 stride Bs32 : t*136+g = t*8+g distinct mod 32

template<bool HALF_OUT>
__global__ __launch_bounds__(256)
void hgemm_kernel(const int* __restrict__ kp, const int* __restrict__ mp,
                  const __half* __restrict__ A, const __half* __restrict__ B,
                  float* __restrict__ Cf, __half* __restrict__ Ch)
{
    if ((int)(blockIdx.y * BM) >= mp[1]) return;
    const int K = kp[1];

    __shared__ unsigned As32[BM * AST];      // [m][k/2] packed half2 (k even, k odd)
    __shared__ unsigned Bs32[(BKT / 2) * BST]; // [k/2][n] packed rows (k even, k odd)

    const int tid  = threadIdx.x;
    const int wid  = tid / 32;
    const int lane = tid % 32;
    const int g    = lane >> 2;
    const int t    = lane & 3;
    const int warpM = wid % 4;     // 32 rows each
    const int warpN = wid / 4;     // 64 cols each

    const int mBase = blockIdx.y * BM;
    const int bCol  = blockIdx.x * BN;
    const size_t cBase = (size_t)mBase * NDIM + bCol;

    float acc[2][8][4];
    #pragma unroll
    for (int i = 0; i < 2; i++)
        #pragma unroll
        for (int j = 0; j < 8; j++)
            #pragma unroll
            for (int q = 0; q < 4; q++) acc[i][j][q] = 0.f;

    for (int bk = 0; bk < K; bk += BKT) {
        // A tile: 128 rows x 32 halves = 128x16 uint32; 512 uint4 tasks, 2/thread
        #pragma unroll
        for (int p = 0; p < 2; p++) {
            int id  = tid + p * 256;
            int row = id >> 2, q = id & 3;
            uint4 v = *(const uint4*)(A + (size_t)(mBase + row) * K + bk + q * 8);
            *(uint4*)(&As32[row * AST + q * 4]) = v;
        }
        // B tile: 32 k-rows x 128 cols -> 16x128 uint32; 1 task of 8 cols per thread
        {
            int k2  = tid >> 4;          // 0..15
            int col = (tid & 15) * 8;    // 0..120
            const __half* bp = B + (size_t)(bk + 2 * k2) * NDIM + bCol + col;
            uint4 ea = *(const uint4*)bp;
            uint4 eb = *(const uint4*)(bp + NDIM);
            const __half2* ha = (const __half2*)&ea;
            const __half2* hb = (const __half2*)&eb;
            unsigned outw[8];
            #pragma unroll
            for (int j = 0; j < 4; j++) {
                __half2 lo = __lows2half2(ha[j], hb[j]);   // {rowEven[c], rowOdd[c]}
                __half2 hi = __highs2half2(ha[j], hb[j]);  // {rowEven[c+1], rowOdd[c+1]}
                outw[2 * j]     = *(unsigned*)&lo;
                outw[2 * j + 1] = *(unsigned*)&hi;
            }
            *(uint4*)(&Bs32[k2 * BST + col])     = *(uint4*)&outw[0];
            *(uint4*)(&Bs32[k2 * BST + col + 4]) = *(uint4*)&outw[4];
        }
        __syncthreads();

        #pragma unroll
        for (int s = 0; s < 2; s++) {        // two k16 steps per 32-k tile
            const int kk = s * 8;            // uint32 index base
            unsigned a[2][4];
            #pragma unroll
            for (int i = 0; i < 2; i++) {
                int mb = warpM * 32 + i * 16;
                a[i][0] = As32[(mb + g)     * AST + kk + t];
                a[i][1] = As32[(mb + g + 8) * AST + kk + t];
                a[i][2] = As32[(mb + g)     * AST + kk + t + 4];
                a[i][3] = As32[(mb + g + 8) * AST + kk + t + 4];
            }
            unsigned b[8][2];
            #pragma unroll
            for (int j = 0; j < 8; j++) {
                int nb = warpN * 64 + j * 8;
                b[j][0] = Bs32[(kk + t)     * BST + nb + g];
                b[j][1] = Bs32[(kk + t + 4) * BST + nb + g];
            }
            #pragma unroll
            for (int i = 0; i < 2; i++)
                #pragma unroll
                for (int j = 0; j < 8; j++) {
                    asm volatile(
                        "mma.sync.aligned.m16n8k16.row.col.f32.f16.f16.f32 "
                        "{%0,%1,%2,%3}, {%4,%5,%6,%7}, {%8,%9}, {%0,%1,%2,%3};"
                        : "+f"(acc[i][j][0]), "+f"(acc[i][j][1]),
                          "+f"(acc[i][j][2]), "+f"(acc[i][j][3])
                        : "r"(a[i][0]), "r"(a[i][1]), "r"(a[i][2]), "r"(a[i][3]),
                          "r"(b[j][0]), "r"(b[j][1]));
                }
        }
        __syncthreads();
    }

    #pragma unroll
    for (int i = 0; i < 2; i++) {
        int row0 = warpM * 32 + i * 16 + g;
        #pragma unroll
        for (int j = 0; j < 8; j++) {
            int col = warpN * 64 + j * 8 + t * 2;
            if (HALF_OUT) {
                __half2 v0 = __floats2half2_rn(acc[i][j][0], acc[i][j][1]);
                __half2 v1 = __floats2half2_rn(acc[i][j][2], acc[i][j][3]);
                *(__half2*)(&Ch[cBase + (size_t)row0 * NDIM + col])       = v0;
                *(__half2*)(&Ch[cBase + (size_t)(row0 + 8) * NDIM + col]) = v1;
            } else {
                *(float2*)(&Cf[cBase + (size_t)row0 * NDIM + col]) =
                    make_float2(acc[i][j][0], acc[i][j][1]);
                *(float2*)(&Cf[cBase + (size_t)(row0 + 8) * NDIM + col]) =
                    make_float2(acc[i][j][2], acc[i][j][3]);
            }
        }
    }
}

// ---------------- launch ----------------
extern "C" void kernel_launch(void* const* d_in, const int* in_sizes, int n_in,
                              void* d_out, int out_size)
{
    (void)in_sizes; (void)n_in; (void)out_size;
    const float* x  = (const float*)d_in[0];
    const float* W1 = (const float*)d_in[1];   // [4096, 2048]
    const float* W2 = (const float*)d_in[2];   // [4096, 4096]
    const float* W3 = (const float*)d_in[3];   // [2048, 4096]
    float* out = (float*)d_out;

    float *h1, *m1, *h2, *m2;
    __half *Et, *A1, *A2, *B1;
    int *idx1, *idx2, *cnt1, *cnt2, *c2048;
    cudaGetSymbolAddress((void**)&h1, g_h1);
    cudaGetSymbolAddress((void**)&m1, g_m1);
    cudaGetSymbolAddress((void**)&h2, g_h2);
    cudaGetSymbolAddress((void**)&m2, g_m2);
    cudaGetSymbolAddress((void**)&Et, g_Et);
    cudaGetSymbolAddress((void**)&A1, g_A1);
    cudaGetSymbolAddress((void**)&A2, g_A2);
    cudaGetSymbolAddress((void**)&B1, g_B1);
    cudaGetSymbolAddress((void**)&idx1, g_idx1);
    cudaGetSymbolAddress((void**)&idx2, g_idx2);
    cudaGetSymbolAddress((void**)&cnt1, g_cnt1);
    cudaGetSymbolAddress((void**)&cnt2, g_cnt2);
    cudaGetSymbolAddress((void**)&c2048, g_c2048);

    // Output offsets (floats)
    const size_t OFF_OUT = 0;
    const size_t OFF_DJM = OFF_OUT + OUTSIZE;
    const size_t OFF_J1  = OFF_DJM + (size_t)INSIZE * OUTSIZE;
    const size_t OFF_J2  = OFF_J1  + (size_t)INSIZE * HSIZE;
    const size_t OFF_J3  = OFF_J2  + (size_t)HSIZE * HSIZE;
    const size_t OFF_J4  = OFF_J3  + (size_t)HSIZE * HSIZE;
    const size_t OFF_J5  = OFF_J4  + (size_t)HSIZE * HSIZE;
    const size_t OFF_J6  = OFF_J5  + (size_t)HSIZE * OUTSIZE;

    // ---- capture-safe fork: side streams joined before return ----
    cudaStream_t sT, sD, sG;
    cudaStreamCreateWithFlags(&sT, cudaStreamNonBlocking);
    cudaStreamCreateWithFlags(&sD, cudaStreamNonBlocking);
    cudaStreamCreateWithFlags(&sG, cudaStreamNonBlocking);
    cudaEvent_t e0, eT, eM, eD, eI, eG;
    cudaEventCreateWithFlags(&e0, cudaEventDisableTiming);
    cudaEventCreateWithFlags(&eT, cudaEventDisableTiming);
    cudaEventCreateWithFlags(&eM, cudaEventDisableTiming);
    cudaEventCreateWithFlags(&eD, cudaEventDisableTiming);
    cudaEventCreateWithFlags(&eI, cudaEventDisableTiming);
    cudaEventCreateWithFlags(&eG, cudaEventDisableTiming);

    cudaEventRecord(e0, 0);
    cudaStreamWaitEvent(sT, e0, 0);
    cudaStreamWaitEvent(sD, e0, 0);

    // Branch T: Jacobian transposes (inputs only), concurrent with GEMVs
    {
        dim3 blk(32, 8);
        transpose_kernel<<<dim3(INSIZE/32, HSIZE/32), blk, 0, sT>>>(W1, out + OFF_J1, HSIZE, INSIZE);
        transpose_kernel<<<dim3(HSIZE/32,  HSIZE/32), blk, 0, sT>>>(W2, out + OFF_J3, HSIZE, HSIZE);
        transpose_kernel<<<dim3(HSIZE/32,  OUTSIZE/32), blk, 0, sT>>>(W3, out + OFF_J5, OUTSIZE, HSIZE);
        cudaEventRecord(eT, sT);
    }

    // Main: forward GEMV chain (fp32; exact masks)
    gemv_kernel<<<HSIZE,   256>>>(W1, x,  h1, m1, INSIZE);
    gemv_kernel<<<HSIZE,   256>>>(W2, h1, h2, m2, HSIZE);
    cudaEventRecord(eM, 0);                       // masks ready
    gemv_kernel<<<OUTSIZE, 256>>>(W3, h2, out + OFF_OUT, nullptr, HSIZE);

    // Branch D: diagonal Jacobian blocks, concurrent with gathers + GEMMs
    {
        size_t nH = ((size_t)HSIZE * HSIZE) / 4;
        size_t nO = ((size_t)OUTSIZE * OUTSIZE) / 4;
        diagfill_kernel<<<(unsigned)((nO + 255) / 256), 256, 0, sD>>>(out + OFF_J6, nullptr, OUTSIZE);
        cudaStreamWaitEvent(sD, eM, 0);
        diagfill_kernel<<<(unsigned)((nH + 255) / 256), 256, 0, sD>>>(out + OFF_J2, m1, HSIZE);
        diagfill_kernel<<<(unsigned)((nH + 255) / 256), 256, 0, sD>>>(out + OFF_J4, m2, HSIZE);
        cudaEventRecord(eD, sD);
    }

    // Main: compaction (needs masks)
    build_idx_kernel<<<1, 1024>>>(m1, HSIZE, idx1, cnt1);
    cudaEventRecord(eI, 0);                       // idx1/cnt1 ready
    build_idx_kernel<<<1, 1024>>>(m2, HSIZE, idx2, cnt2);

    // Branch G: A2 gather (GEMM2 operand) overlaps GEMM1
    cudaStreamWaitEvent(sG, eI, 0);
    cudaStreamWaitEvent(sG, eT, 0);
    gatherC_kernel<<<INSIZE, 256, 0, sG>>>(out + OFF_J1, HSIZE, idx1, cnt1, A2);
    cudaEventRecord(eG, sG);

    // Main: GEMM1 operands, then GEMMs
    cudaStreamWaitEvent(0, eT, 0);
    gatherRC_kernel<<<HSIZE, 256>>>(out + OFF_J3, HSIZE, idx1, idx2, cnt1, cnt2, A1);
    gatherR_kernel<<<HSIZE, 256>>>(out + OFF_J5, OUTSIZE, idx2, cnt2, B1, OUTSIZE);

    // GEMM1: Et[n1p, 2048] = A1 @ B1   (K = n2p, M-limit = n1p), fp16 out
    hgemm_kernel<true><<<dim3(NDIM / BN, HSIZE / BM), 256>>>(cnt2, cnt1, A1, B1, nullptr, Et);
    // GEMM2: DJM[2048, 2048] = A2 @ Et (K = n1p), fp32 out
    cudaStreamWaitEvent(0, eG, 0);
    hgemm_kernel<false><<<dim3(NDIM / BN, INSIZE / BM), 256>>>(cnt1, c2048, A2, Et, out + OFF_DJM, nullptr);

    cudaStreamWaitEvent(0, eD, 0);

    cudaEventDestroy(e0); cudaEventDestroy(eT); cudaEventDestroy(eM);
    cudaEventDestroy(eD); cudaEventDestroy(eI); cudaEventDestroy(eG);
    cudaStreamDestroy(sT); cudaStreamDestroy(sD); cudaStreamDestroy(sG);
}

// round 10
// speedup vs baseline: 1.8639x; 1.0354x over previous
#include <cuda_runtime.h>
#include <cuda_fp16.h>
#include <cstddef>

// Problem dims (fixed by the dataset)
#define INSIZE  2048
#define HSIZE   4096
#define OUTSIZE 2048

// ---------------- device scratch (no allocations allowed) ----------------
__device__ float  g_h1[HSIZE];
__device__ float  g_m1[HSIZE];
__device__ float  g_h2[HSIZE];
__device__ float  g_m2[HSIZE];
__device__ __half g_Et[(size_t)HSIZE * OUTSIZE];   // Et[n1pad][2048] fp16
__device__ __half g_A1[(size_t)HSIZE * HSIZE];     // W2^T[idx1][idx2] fp16
__device__ __half g_A2[(size_t)INSIZE * HSIZE];    // W1^T[:, idx1] fp16
__device__ __half g_B1[(size_t)HSIZE * OUTSIZE];   // W3^T rows idx2 fp16
__device__ int    g_idx1[HSIZE];
__device__ int    g_idx2[HSIZE];
__device__ int    g_cnt1[2];   // [raw, padded-to-64]
__device__ int    g_cnt2[2];
__device__ int    g_c2048[2] = {INSIZE, INSIZE};

// ---------------- fp32 GEMV: z = W @ v, optional ReLU mask ----------------
__global__ void gemv_kernel(const float* __restrict__ W, const float* __restrict__ v,
                            float* __restrict__ h, float* __restrict__ mask, int K)
{
    int row = blockIdx.x;
    const float* w = W + (size_t)row * K;
    float acc = 0.f;
    for (int i = threadIdx.x * 4; i < K; i += blockDim.x * 4) {
        float4 a = *(const float4*)(w + i);
        float4 b = *(const float4*)(v + i);
        acc += a.x * b.x + a.y * b.y + a.z * b.z + a.w * b.w;
    }
    __shared__ float red[256];
    red[threadIdx.x] = acc;
    __syncthreads();
    for (int s = 128; s > 0; s >>= 1) {
        if (threadIdx.x < s) red[threadIdx.x] += red[threadIdx.x + s];
        __syncthreads();
    }
    if (threadIdx.x == 0) {
        float z = red[0];
        if (mask) {
            float m = z > 0.f ? 1.f : 0.f;
            mask[row] = m;
            h[row]    = z * m;
        } else {
            h[row] = z;
        }
    }
}

// ---------------- transpose: in[R,C] -> out[C,R] ----------------
__global__ void transpose_kernel(const float* __restrict__ in, float* __restrict__ out,
                                 int R, int C)
{
    __shared__ float tile[32][33];
    int x = blockIdx.x * 32 + threadIdx.x;
    int y = blockIdx.y * 32 + threadIdx.y;
    #pragma unroll
    for (int j = 0; j < 32; j += 8)
        tile[threadIdx.y + j][threadIdx.x] = in[(size_t)(y + j) * C + x];
    __syncthreads();
    int ox = blockIdx.y * 32 + threadIdx.x;
    int oy = blockIdx.x * 32 + threadIdx.y;
    #pragma unroll
    for (int j = 0; j < 32; j += 8)
        out[(size_t)(oy + j) * R + ox] = tile[threadIdx.x][threadIdx.y + j];
}

// ---------------- diag fill: out[N,N] = diag(d) (d==nullptr -> identity) ----------------
__global__ void diagfill_kernel(float* __restrict__ out, const float* __restrict__ d, int N)
{
    size_t idx = ((size_t)blockIdx.x * blockDim.x + threadIdx.x) * 4;
    size_t total = (size_t)N * N;
    if (idx >= total) return;
    size_t row = idx / N;
    size_t col = idx - row * N;
    float4 v = make_float4(0.f, 0.f, 0.f, 0.f);
    if (row >= col && row < col + 4) {
        float dv = d ? d[row] : 1.0f;
        ((float*)&v)[row - col] = dv;
    }
    *(float4*)(out + idx) = v;
}

// ---------------- build sorted index list of nonzero mask entries ----------------
__global__ void build_idx_kernel(const float* __restrict__ mask, int n,
                                 int* __restrict__ idx, int* __restrict__ cnt)
{
    __shared__ int sdata[1024];
    __shared__ int sbase;
    int tid = threadIdx.x;
    if (tid == 0) sbase = 0;
    __syncthreads();
    for (int chunk = 0; chunk < n; chunk += 1024) {
        int i = chunk + tid;
        int flag = (i < n && mask[i] != 0.f) ? 1 : 0;
        sdata[tid] = flag;
        __syncthreads();
        #pragma unroll
        for (int off = 1; off < 1024; off <<= 1) {
            int v = (tid >= off) ? sdata[tid - off] : 0;
            __syncthreads();
            sdata[tid] += v;
            __syncthreads();
        }
        int incl  = sdata[tid];
        int total = sdata[1023];
        if (flag) idx[sbase + incl - 1] = i;
        __syncthreads();
        if (tid == 0) sbase += total;
        __syncthreads();
    }
    if (tid == 0) {
        cnt[0] = sbase;
        cnt[1] = (sbase + 63) & ~63;   // pad to 64 (BKT multiple)
    }
}

// ---------------- gather kernels -> fp16 outputs (pad exact zeros) ----------------
__global__ void gatherRC_kernel(const float* __restrict__ src, int sld,
                                const int* __restrict__ ridx, const int* __restrict__ cidx,
                                const int* __restrict__ cntr, const int* __restrict__ cntc,
                                __half* __restrict__ out)
{
    int r = blockIdx.x;
    int rc = cntr[0], rp = cntr[1];
    int cc = cntc[0], cp = cntc[1];
    if (r >= rp) return;
    bool ok = (r < rc);
    const float* s = src + (size_t)(ok ? ridx[r] : 0) * sld;
    __half* o = out + (size_t)r * cp;
    for (int j = threadIdx.x; j < cp; j += blockDim.x)
        o[j] = (ok && j < cc) ? __float2half_rn(s[cidx[j]]) : __float2half_rn(0.f);
}

__global__ void gatherC_kernel(const float* __restrict__ src, int sld,
                               const int* __restrict__ cidx, const int* __restrict__ cntc,
                               __half* __restrict__ out)
{
    int r = blockIdx.x;
    int cc = cntc[0], cp = cntc[1];
    const float* s = src + (size_t)r * sld;
    __half* o = out + (size_t)r * cp;
    for (int j = threadIdx.x; j < cp; j += blockDim.x)
        o[j] = (j < cc) ? __float2half_rn(s[cidx[j]]) : __float2half_rn(0.f);
}

__global__ void gatherR_kernel(const float* __restrict__ src, int sld,
                               const int* __restrict__ ridx, const int* __restrict__ cntr,
                               __half* __restrict__ out, int ncols)
{
    int r = blockIdx.x;
    int rc = cntr[0], rp = cntr[1];
    if (r >= rp) return;
    bool ok = (r < rc);
    const float* s = src + (size_t)(ok ? ridx[r] : 0) * sld;
    __half* o = out + (size_t)r * ncols;
    for (int j = threadIdx.x * 4; j < ncols; j += blockDim.x * 4) {
        float4 v = ok ? *(const float4*)(s + j) : make_float4(0.f, 0.f, 0.f, 0.f);
        __half2 lo = __floats2half2_rn(v.x, v.y);
        __half2 hi = __floats2half2_rn(v.z, v.w);
        *(__half2*)(o + j)     = lo;
        *(__half2*)(o + j + 2) = hi;
    }
}

// ---------------- fp16 tensor-core GEMM: m16n8k16, 8 warps x 32x64, BKT=64 ----------------
// C[M,N] = A[M,K] @ B[K,N]; A,B fp16 (K padded to 64); K = kp[1]; blocks with
// row-base >= mp[1] exit. N fixed = 2048. Output fp32 or fp16 (template).
#define BM  128
#define BN  128
#define BKT 64      // k elements per tile
#define NDIM 2048
#define AST 36      // uint32 stride As32 (32 data + 4 pad): g*36+t = 4g+t distinct mod 32
#define BST 136     // uint32 stride Bs32: t*136+g = 8t+g distinct mod 32

template<bool HALF_OUT>
__global__ __launch_bounds__(256)
void hgemm_kernel(const int* __restrict__ kp, const int* __restrict__ mp,
                  const __half* __restrict__ A, const __half* __restrict__ B,
                  float* __restrict__ Cf, __half* __restrict__ Ch)
{
    if ((int)(blockIdx.y * BM) >= mp[1]) return;
    const int K = kp[1];

    __shared__ unsigned As32[BM * AST];        // [m][k/2] packed half2 (k even, k odd)
    __shared__ unsigned Bs32[(BKT / 2) * BST]; // [k/2][n] packed from row pairs

    const int tid  = threadIdx.x;
    const int wid  = tid / 32;
    const int lane = tid % 32;
    const int g    = lane >> 2;
    const int t    = lane & 3;
    const int warpM = wid % 4;     // 32 rows each
    const int warpN = wid / 4;     // 64 cols each

    const int mBase = blockIdx.y * BM;
    const int bCol  = blockIdx.x * BN;
    const size_t cBase = (size_t)mBase * NDIM + bCol;

    float acc[2][8][4];
    #pragma unroll
    for (int i = 0; i < 2; i++)
        #pragma unroll
        for (int j = 0; j < 8; j++)
            #pragma unroll
            for (int q = 0; q < 4; q++) acc[i][j][q] = 0.f;

    for (int bk = 0; bk < K; bk += BKT) {
        // A tile: 128 rows x 64 halves = 8 uint4 per row; 1024 tasks, 4/thread
        #pragma unroll
        for (int p = 0; p < 4; p++) {
            int id  = tid + p * 256;
            int row = id >> 3, q = id & 7;
            uint4 v = *(const uint4*)(A + (size_t)(mBase + row) * K + bk + q * 8);
            *(uint4*)(&As32[row * AST + q * 4]) = v;
        }
        // B tile: 64 k-rows x 128 cols -> 32x128 uint32; 2 passes of 8 cols/thread
        #pragma unroll
        for (int p = 0; p < 2; p++) {
            int id  = tid + p * 256;
            int k2  = id >> 4;           // 0..31
            int col = (id & 15) * 8;     // 0..120
            const __half* bp = B + (size_t)(bk + 2 * k2) * NDIM + bCol + col;
            uint4 ea = *(const uint4*)bp;
            uint4 eb = *(const uint4*)(bp + NDIM);
            const __half2* ha = (const __half2*)&ea;
            const __half2* hb = (const __half2*)&eb;
            unsigned outw[8];
            #pragma unroll
            for (int j = 0; j < 4; j++) {
                __half2 lo = __lows2half2(ha[j], hb[j]);   // {rowEven[c], rowOdd[c]}
                __half2 hi = __highs2half2(ha[j], hb[j]);  // {rowEven[c+1], rowOdd[c+1]}
                outw[2 * j]     = *(unsigned*)&lo;
                outw[2 * j + 1] = *(unsigned*)&hi;
            }
            *(uint4*)(&Bs32[k2 * BST + col])     = *(uint4*)&outw[0];
            *(uint4*)(&Bs32[k2 * BST + col + 4]) = *(uint4*)&outw[4];
        }
        __syncthreads();

        #pragma unroll
        for (int s = 0; s < 4; s++) {        // four k16 steps per 64-k tile
            const int kk = s * 8;            // uint32 index base
            unsigned a[2][4];
            #pragma unroll
            for (int i = 0; i < 2; i++) {
                int mb = warpM * 32 + i * 16;
                a[i][0] = As32[(mb + g)     * AST + kk + t];
                a[i][1] = As32[(mb + g + 8) * AST + kk + t];
                a[i][2] = As32[(mb + g)     * AST + kk + t + 4];
                a[i][3] = As32[(mb + g + 8) * AST + kk + t + 4];
            }
            unsigned b[8][2];
            #pragma unroll
            for (int j = 0; j < 8; j++) {
                int nb = warpN * 64 + j * 8;
                b[j][0] = Bs32[(kk + t)     * BST + nb + g];
                b[j][1] = Bs32[(kk + t + 4) * BST + nb + g];
            }
            #pragma unroll
            for (int i = 0; i < 2; i++)
                #pragma unroll
                for (int j = 0; j < 8; j++) {
                    asm volatile(
                        "mma.sync.aligned.m16n8k16.row.col.f32.f16.f16.f32 "
                        "{%0,%1,%2,%3}, {%4,%5,%6,%7}, {%8,%9}, {%0,%1,%2,%3};"
                        : "+f"(acc[i][j][0]), "+f"(acc[i][j][1]),
                          "+f"(acc[i][j][2]), "+f"(acc[i][j][3])
                        : "r"(a[i][0]), "r"(a[i][1]), "r"(a[i][2]), "r"(a[i][3]),
                          "r"(b[j][0]), "r"(b[j][1]));
                }
        }
        __syncthreads();
    }

    #pragma unroll
    for (int i = 0; i < 2; i++) {
        int row0 = warpM * 32 + i * 16 + g;
        #pragma unroll
        for (int j = 0; j < 8; j++) {
            int col = warpN * 64 + j * 8 + t * 2;
            if (HALF_OUT) {
                __half2 v0 = __floats2half2_rn(acc[i][j][0], acc[i][j][1]);
                __half2 v1 = __floats2half2_rn(acc[i][j][2], acc[i][j][3]);
                *(__half2*)(&Ch[cBase + (size_t)row0 * NDIM + col])       = v0;
                *(__half2*)(&Ch[cBase + (size_t)(row0 + 8) * NDIM + col]) = v1;
            } else {
                *(float2*)(&Cf[cBase + (size_t)row0 * NDIM + col]) =
                    make_float2(acc[i][j][0], acc[i][j][1]);
                *(float2*)(&Cf[cBase + (size_t)(row0 + 8) * NDIM + col]) =
                    make_float2(acc[i][j][2], acc[i][j][3]);
            }
        }
    }
}

// ---------------- launch ----------------
extern "C" void kernel_launch(void* const* d_in, const int* in_sizes, int n_in,
                              void* d_out, int out_size)
{
    (void)in_sizes; (void)n_in; (void)out_size;
    const float* x  = (const float*)d_in[0];
    const float* W1 = (const float*)d_in[1];   // [4096, 2048]
    const float* W2 = (const float*)d_in[2];   // [4096, 4096]
    const float* W3 = (const float*)d_in[3];   // [2048, 4096]
    float* out = (float*)d_out;

    float *h1, *m1, *h2, *m2;
    __half *Et, *A1, *A2, *B1;
    int *idx1, *idx2, *cnt1, *cnt2, *c2048;
    cudaGetSymbolAddress((void**)&h1, g_h1);
    cudaGetSymbolAddress((void**)&m1, g_m1);
    cudaGetSymbolAddress((void**)&h2, g_h2);
    cudaGetSymbolAddress((void**)&m2, g_m2);
    cudaGetSymbolAddress((void**)&Et, g_Et);
    cudaGetSymbolAddress((void**)&A1, g_A1);
    cudaGetSymbolAddress((void**)&A2, g_A2);
    cudaGetSymbolAddress((void**)&B1, g_B1);
    cudaGetSymbolAddress((void**)&idx1, g_idx1);
    cudaGetSymbolAddress((void**)&idx2, g_idx2);
    cudaGetSymbolAddress((void**)&cnt1, g_cnt1);
    cudaGetSymbolAddress((void**)&cnt2, g_cnt2);
    cudaGetSymbolAddress((void**)&c2048, g_c2048);

    // Output offsets (floats)
    const size_t OFF_OUT = 0;
    const size_t OFF_DJM = OFF_OUT + OUTSIZE;
    const size_t OFF_J1  = OFF_DJM + (size_t)INSIZE * OUTSIZE;
    const size_t OFF_J2  = OFF_J1  + (size_t)INSIZE * HSIZE;
    const size_t OFF_J3  = OFF_J2  + (size_t)HSIZE * HSIZE;
    const size_t OFF_J4  = OFF_J3  + (size_t)HSIZE * HSIZE;
    const size_t OFF_J5  = OFF_J4  + (size_t)HSIZE * HSIZE;
    const size_t OFF_J6  = OFF_J5  + (size_t)HSIZE * OUTSIZE;

    // ---- capture-safe fork: side streams joined before return ----
    cudaStream_t sT, sD, sG;
    cudaStreamCreateWithFlags(&sT, cudaStreamNonBlocking);
    cudaStreamCreateWithFlags(&sD, cudaStreamNonBlocking);
    cudaStreamCreateWithFlags(&sG, cudaStreamNonBlocking);
    cudaEvent_t e0, eT, eM1, eM2, eD, eG;
    cudaEventCreateWithFlags(&e0,  cudaEventDisableTiming);
    cudaEventCreateWithFlags(&eT,  cudaEventDisableTiming);
    cudaEventCreateWithFlags(&eM1, cudaEventDisableTiming);
    cudaEventCreateWithFlags(&eM2, cudaEventDisableTiming);
    cudaEventCreateWithFlags(&eD,  cudaEventDisableTiming);
    cudaEventCreateWithFlags(&eG,  cudaEventDisableTiming);

    cudaEventRecord(e0, 0);
    cudaStreamWaitEvent(sT, e0, 0);
    cudaStreamWaitEvent(sD, e0, 0);

    // Branch T: Jacobian transposes (inputs only), concurrent with GEMVs
    {
        dim3 blk(32, 8);
        transpose_kernel<<<dim3(INSIZE/32, HSIZE/32), blk, 0, sT>>>(W1, out + OFF_J1, HSIZE, INSIZE);
        transpose_kernel<<<dim3(HSIZE/32,  HSIZE/32), blk, 0, sT>>>(W2, out + OFF_J3, HSIZE, HSIZE);
        transpose_kernel<<<dim3(HSIZE/32,  OUTSIZE/32), blk, 0, sT>>>(W3, out + OFF_J5, OUTSIZE, HSIZE);
        cudaEventRecord(eT, sT);
    }

    // Main: forward GEMV chain (fp32; exact masks). GEMV3 moved off critical path.
    gemv_kernel<<<HSIZE, 256>>>(W1, x,  h1, m1, INSIZE);
    cudaEventRecord(eM1, 0);                      // m1, h1 ready
    gemv_kernel<<<HSIZE, 256>>>(W2, h1, h2, m2, HSIZE);
    cudaEventRecord(eM2, 0);                      // m2, h2 ready

    // Branch D: identity block early; then GEMV3 + mask diagonals (off critical path)
    {
        size_t nH = ((size_t)HSIZE * HSIZE) / 4;
        size_t nO = ((size_t)OUTSIZE * OUTSIZE) / 4;
        diagfill_kernel<<<(unsigned)((nO + 255) / 256), 256, 0, sD>>>(out + OFF_J6, nullptr, OUTSIZE);
        cudaStreamWaitEvent(sD, eM2, 0);
        gemv_kernel<<<OUTSIZE, 256, 0, sD>>>(W3, h2, out + OFF_OUT, nullptr, HSIZE);
        diagfill_kernel<<<(unsigned)((nH + 255) / 256), 256, 0, sD>>>(out + OFF_J2, m1, HSIZE);
        diagfill_kernel<<<(unsigned)((nH + 255) / 256), 256, 0, sD>>>(out + OFF_J4, m2, HSIZE);
        cudaEventRecord(eD, sD);
    }

    // Branch G: build_idx1 overlaps GEMV2; then A2 gather overlaps GEMM1 operands/GEMM1
    cudaStreamWaitEvent(sG, eM1, 0);
    build_idx_kernel<<<1, 1024, 0, sG>>>(m1, HSIZE, idx1, cnt1);
    cudaStreamWaitEvent(sG, eT, 0);
    gatherC_kernel<<<INSIZE, 256, 0, sG>>>(out + OFF_J1, HSIZE, idx1, cnt1, A2);
    cudaEventRecord(eG, sG);

    // Main: build_idx2, GEMM1 operands, GEMMs
    build_idx_kernel<<<1, 1024>>>(m2, HSIZE, idx2, cnt2);
    cudaStreamWaitEvent(0, eT, 0);
    cudaStreamWaitEvent(0, eG, 0);   // idx1 ready (A2 gather continues on sG concurrently? no — eG after gather; wait only on idx1 via sG order)
    gatherRC_kernel<<<HSIZE, 256>>>(out + OFF_J3, HSIZE, idx1, idx2, cnt1, cnt2, A1);
    gatherR_kernel<<<HSIZE, 256>>>(out + OFF_J5, OUTSIZE, idx2, cnt2, B1, OUTSIZE);

    // GEMM1: Et[n1p, 2048] = A1 @ B1   (K = n2p, M-limit = n1p), fp16 out
    hgemm_kernel<true><<<dim3(NDIM / BN, HSIZE / BM), 256>>>(cnt2, cnt1, A1, B1, nullptr, Et);
    // GEMM2: DJM[2048, 2048] = A2 @ Et (K = n1p), fp32 out
    hgemm_kernel<false><<<dim3(NDIM / BN, INSIZE / BM), 256>>>(cnt1, c2048, A2, Et, out + OFF_DJM, nullptr);

    cudaStreamWaitEvent(0, eD, 0);

    cudaEventDestroy(e0); cudaEventDestroy(eT); cudaEventDestroy(eM1);
    cudaEventDestroy(eM2); cudaEventDestroy(eD); cudaEventDestroy(eG);
    cudaStreamDestroy(sT); cudaStreamDestroy(sD); cudaStreamDestroy(sG);
}